// round 4
// baseline (speedup 1.0000x reference)
#include <cuda_runtime.h>
#include <math.h>

#define B_   64
#define T_   2048
#define M_   512
#define P_   512
#define K2_  1024   // 2*P

// ---- scratch (no allocations allowed) ----
__device__ float g_base[B_ * M_];     // ds_proj + b_wd + b_ud, per (b, m)
__device__ float g_logits[B_ * T_];   // l[b][t] before softmax

// ============================================================
// Kernel 1: base[b][m] = concat(h,c)[b] . W_d[:,m] + b_wd[m] + b_ud[m]
// ============================================================
__global__ void base_kernel(const float* __restrict__ h,
                            const float* __restrict__ c,
                            const float* __restrict__ Wd,
                            const float* __restrict__ bwd,
                            const float* __restrict__ bud)
{
    int b = blockIdx.x;
    __shared__ float ds[K2_];
    for (int i = threadIdx.x; i < P_; i += blockDim.x) {
        ds[i]       = h[b * P_ + i];
        ds[P_ + i]  = c[b * P_ + i];
    }
    __syncthreads();
    for (int m = threadIdx.x; m < M_; m += blockDim.x) {
        float s = bwd[m] + bud[m];
        #pragma unroll 4
        for (int k = 0; k < K2_; k++)
            s += ds[k] * Wd[(size_t)k * M_ + m];
        g_base[b * M_ + m] = s;
    }
}

// ============================================================
// Kernel 2: fused  enc @ U_d  -> tanh(+base) -> dot v_d  -> logits
// Tile: TT=32 t-rows per block, m in chunks of TM=128, k tiles of TK=16.
// 256 threads, microtile 2t x 8m per thread.
// ============================================================
#define TT 32
#define TM 128
#define TK 16
#define ENC_STRIDE (M_ + 4)                     // 516, multiple of 4 -> float4 ok
#define SMEM_FLOATS (TT * ENC_STRIDE + TK * TM) // 16512 + 2048
#define SMEM_BYTES  (SMEM_FLOATS * 4)           // 74240 bytes

__global__ void __launch_bounds__(256, 1)
attn_main(const float* __restrict__ enc,
          const float* __restrict__ U,
          const float* __restrict__ v,
          const float* __restrict__ bvd)
{
    extern __shared__ float smem[];
    float* sEnc = smem;                 // [TT][ENC_STRIDE]
    float* sU   = smem + TT * ENC_STRIDE; // [TK][TM]

    const int b  = blockIdx.y;
    const int t0 = blockIdx.x * TT;
    const float* encB = enc + ((size_t)b * T_ + t0) * M_;

    // Load enc tile: 32 rows x 512 floats = 4096 float4
    for (int i = threadIdx.x; i < TT * (M_ / 4); i += 256) {
        int row = i >> 7;          // /128
        int c4  = i & 127;
        float4 val = ((const float4*)(encB + (size_t)row * M_))[c4];
        *((float4*)&sEnc[row * ENC_STRIDE + c4 * 4]) = val;
    }
    // (first __syncthreads in the k-loop orders this before compute)

    const int mg = threadIdx.x & 15;   // m-group: 8 cols each
    const int tg = threadIdx.x >> 4;   // t-group: 2 rows each
    const int tA = tg * 2, tB = tg * 2 + 1;

    const float* base = g_base + b * M_;
    float lA = 0.f, lB = 0.f;

    for (int m0 = 0; m0 < M_; m0 += TM) {
        float accA[8], accB[8];
        #pragma unroll
        for (int j = 0; j < 8; j++) { accA[j] = 0.f; accB[j] = 0.f; }

        for (int kt = 0; kt < M_; kt += TK) {
            __syncthreads();   // prev compute done (and enc load on first iter)
            // Load U tile [TK][TM]: 16*32 = 512 float4, 2 per thread
            for (int i = threadIdx.x; i < TK * (TM / 4); i += 256) {
                int r  = i >> 5;   // /32
                int c4 = i & 31;
                *((float4*)&sU[r * TM + c4 * 4]) =
                    ((const float4*)(U + (size_t)(kt + r) * M_ + m0))[c4];
            }
            __syncthreads();

            #pragma unroll
            for (int kk = 0; kk < TK; kk++) {
                float eA = sEnc[tA * ENC_STRIDE + kt + kk];
                float eB = sEnc[tB * ENC_STRIDE + kt + kk];
                float4 u0 = *((const float4*)&sU[kk * TM + mg * 8]);
                float4 u1 = *((const float4*)&sU[kk * TM + mg * 8 + 4]);
                accA[0] += eA * u0.x; accA[1] += eA * u0.y;
                accA[2] += eA * u0.z; accA[3] += eA * u0.w;
                accA[4] += eA * u1.x; accA[5] += eA * u1.y;
                accA[6] += eA * u1.z; accA[7] += eA * u1.w;
                accB[0] += eB * u0.x; accB[1] += eB * u0.y;
                accB[2] += eB * u0.z; accB[3] += eB * u0.w;
                accB[4] += eB * u1.x; accB[5] += eB * u1.y;
                accB[6] += eB * u1.z; accB[7] += eB * u1.w;
            }
        }

        // fused epilogue for this m chunk: tanh(acc + base) * v
        #pragma unroll
        for (int j = 0; j < 8; j++) {
            int m = m0 + mg * 8 + j;
            float bb = base[m];
            float vv = v[m];
            lA += tanhf(accA[j] + bb) * vv;
            lB += tanhf(accB[j] + bb) * vv;
        }
    }

    // reduce over the 16 m-groups (lane bits 0..3 within the warp)
    #pragma unroll
    for (int off = 8; off; off >>= 1) {
        lA += __shfl_xor_sync(0xffffffffu, lA, off);
        lB += __shfl_xor_sync(0xffffffffu, lB, off);
    }
    if (mg == 0) {
        float bv = bvd[0];
        g_logits[b * T_ + t0 + tA] = lA + bv;
        g_logits[b * T_ + t0 + tB] = lB + bv;
    }
}

// ============================================================
// Kernel 3: softmax over T per batch
// ============================================================
__global__ void softmax_kernel(float* __restrict__ out)
{
    const int b = blockIdx.x;
    const int tid = threadIdx.x;
    const float* l = g_logits + b * T_;
    __shared__ float red[256];

    float vals[T_ / 256];
    float mx = -1e30f;
    #pragma unroll
    for (int j = 0; j < T_ / 256; j++) {
        vals[j] = l[tid + j * 256];
        mx = fmaxf(mx, vals[j]);
    }
    red[tid] = mx; __syncthreads();
    for (int s = 128; s; s >>= 1) {
        if (tid < s) red[tid] = fmaxf(red[tid], red[tid + s]);
        __syncthreads();
    }
    mx = red[0];
    __syncthreads();

    float sum = 0.f;
    #pragma unroll
    for (int j = 0; j < T_ / 256; j++) {
        vals[j] = expf(vals[j] - mx);
        sum += vals[j];
    }
    red[tid] = sum; __syncthreads();
    for (int s = 128; s; s >>= 1) {
        if (tid < s) red[tid] += red[tid + s];
        __syncthreads();
    }
    float inv = 1.0f / red[0];
    #pragma unroll
    for (int j = 0; j < T_ / 256; j++)
        out[b * T_ + tid + j * 256] = vals[j] * inv;
}

// ============================================================
extern "C" void kernel_launch(void* const* d_in, const int* in_sizes, int n_in,
                              void* d_out, int out_size)
{
    const float* h   = (const float*)d_in[0];  // hidden_state (B,P)
    const float* c   = (const float*)d_in[1];  // cell_state   (B,P)
    const float* enc = (const float*)d_in[2];  // encoder_h    (B,T,M)
    const float* Wd  = (const float*)d_in[3];  // W_d (2P,M)
    const float* bwd = (const float*)d_in[4];  // b_wd (M)
    const float* U   = (const float*)d_in[5];  // U_d (M,M)
    const float* bud = (const float*)d_in[6];  // b_ud (M)
    const float* v   = (const float*)d_in[7];  // v_d (M,1)
    const float* bvd = (const float*)d_in[8];  // b_vd (1)
    float* out = (float*)d_out;                // (B,T,1)

    cudaFuncSetAttribute(attn_main, cudaFuncAttributeMaxDynamicSharedMemorySize, SMEM_BYTES);

    base_kernel<<<B_, 256>>>(h, c, Wd, bwd, bud);
    attn_main<<<dim3(T_ / TT, B_), 256, SMEM_BYTES>>>(enc, U, v, bvd);
    softmax_kernel<<<B_, 256>>>(out);
}

// round 7
// speedup vs baseline: 10.0043x; 10.0043x over previous
#include <cuda_runtime.h>
#include <cuda_bf16.h>
#include <cuda_fp16.h>
#include <math.h>
#include <stdint.h>

#define B_   64
#define T_   2048
#define M_   512
#define P_   512
#define K2_  1024
#define R_   (B_ * T_)

// ---------------- device scratch (no allocations allowed) ----------------
__device__ float g_base[B_ * M_];
__device__ float g_logits[B_ * T_];
__device__ __align__(16) __nv_bfloat16 gU_hi[M_ * M_];   // [n][k]
__device__ __align__(16) __nv_bfloat16 gU_lo[M_ * M_];   // [n][k]

// ---------------- helpers ----------------
__device__ __forceinline__ uint32_t smem_u32(const void* p) {
    uint32_t a;
    asm("{ .reg .u64 t; cvta.to.shared.u64 t, %1; cvt.u32.u64 %0, t; }" : "=r"(a) : "l"(p));
    return a;
}
// bf16x2: lo = e0, hi = e1
__device__ __forceinline__ uint32_t pack2bf(float e0, float e1) {
    uint32_t d;
    asm("cvt.rn.bf16x2.f32 %0, %1, %2;" : "=r"(d) : "f"(e1), "f"(e0));
    return d;
}
// f16x2: lo = e0, hi = e1
__device__ __forceinline__ uint32_t pack2h(float e0, float e1) {
    uint32_t d;
    asm("cvt.rn.f16x2.f32 %0, %1, %2;" : "=r"(d) : "f"(e1), "f"(e0));
    return d;
}
__device__ __forceinline__ uint32_t tanh2(uint32_t x) {
    uint32_t d;
    asm("tanh.approx.f16x2 %0, %1;" : "=r"(d) : "r"(x));
    return d;
}
__device__ __forceinline__ uint32_t hfma2(uint32_t a, uint32_t b, uint32_t c) {
    uint32_t d;
    asm("fma.rn.f16x2 %0, %1, %2, %3;" : "=r"(d) : "r"(a), "r"(b), "r"(c));
    return d;
}
__device__ __forceinline__ float hsum2(uint32_t h) {
    __half2 v = *reinterpret_cast<__half2*>(&h);
    return __low2float(v) + __high2float(v);
}
#define LDSM4(r0, r1, r2, r3, addr)                                          \
    asm volatile("ldmatrix.sync.aligned.m8n8.x4.shared.b16 {%0,%1,%2,%3}, [%4];" \
        : "=r"(r0), "=r"(r1), "=r"(r2), "=r"(r3) : "r"(addr))

__device__ __forceinline__ void mma16816(float* c, const uint32_t* a, const uint32_t* b) {
    asm volatile(
        "mma.sync.aligned.m16n8k16.row.col.f32.bf16.bf16.f32 "
        "{%0,%1,%2,%3}, {%4,%5,%6,%7}, {%8,%9}, {%0,%1,%2,%3};"
        : "+f"(c[0]), "+f"(c[1]), "+f"(c[2]), "+f"(c[3])
        : "r"(a[0]), "r"(a[1]), "r"(a[2]), "r"(a[3]), "r"(b[0]), "r"(b[1]));
}

// ---------------- smem layout (bytes) ----------------
#define OFF_EH  0                       // enc hi: 64 x 512 bf16 = 65536
#define OFF_EL  65536                   // enc lo: 65536
#define OFF_UH  131072                  // U tile hi: 128n x 128k bf16 = 32768
#define OFF_UL  163840                  // U tile lo: 32768
#define OFF_BH  196608                  // base hi bf16 [512] = 1024
#define OFF_BL  197632                  // base lo bf16 [512] = 1024
#define OFF_V2  198656                  // v pairs f16x2 [256] = 1024
#define OFF_LG  199680                  // logits f32 [64] = 256
#define SMEM_TOTAL 199936

// ============================================================
// Kernel 0a: transpose + hi/lo split of U into gU_hi/gU_lo ([n][k])
// ============================================================
__global__ void prep_U(const float* __restrict__ U) {
    __shared__ float tile[32][33];
    int n0 = blockIdx.x * 32, k0 = blockIdx.y * 32;
    int tx = threadIdx.x & 31, ty = threadIdx.x >> 5;
    #pragma unroll
    for (int i = 0; i < 4; i++) {
        int k = ty + i * 8;
        tile[k][tx] = U[(size_t)(k0 + k) * M_ + n0 + tx];
    }
    __syncthreads();
    #pragma unroll
    for (int i = 0; i < 4; i++) {
        int n = ty + i * 8;
        float x = tile[tx][n];
        __nv_bfloat16 h = __float2bfloat16(x);
        float hf = __uint_as_float(((uint32_t)__bfloat16_as_ushort(h)) << 16);
        __nv_bfloat16 l = __float2bfloat16(x - hf);
        size_t o = (size_t)(n0 + n) * M_ + k0 + tx;
        gU_hi[o] = h;
        gU_lo[o] = l;
    }
}

// ============================================================
// Kernel 0b: base[b][m] = concat(h,c).W_d[:,m] + b_wd + b_ud
// ============================================================
__global__ void base2(const float* __restrict__ h, const float* __restrict__ c,
                      const float* __restrict__ Wd, const float* __restrict__ bwd,
                      const float* __restrict__ bud) {
    int b = blockIdx.x, m0 = blockIdx.y * 64;
    __shared__ float ds[K2_];
    __shared__ float part[4][64];
    int tid = threadIdx.x;
    for (int i = tid; i < P_; i += 256) { ds[i] = h[b * P_ + i]; ds[P_ + i] = c[b * P_ + i]; }
    __syncthreads();
    int kg = tid >> 6, mi = tid & 63;
    int m = m0 + mi;
    float s = 0.f;
    #pragma unroll 8
    for (int k = kg * 256; k < kg * 256 + 256; k++)
        s += ds[k] * Wd[(size_t)k * M_ + m];
    part[kg][mi] = s;
    __syncthreads();
    if (kg == 0)
        g_base[b * M_ + m] = part[0][mi] + part[1][mi] + part[2][mi] + part[3][mi]
                           + bwd[m] + bud[m];
}

// ============================================================
// Kernel 1: mma.sync bf16 split GEMM (64 tok x 512 n, K=512)
//           + fused bias-in-GEMM + tanh.f16x2 + dot(v) epilogue
// ============================================================
__global__ void __launch_bounds__(256, 1)
attn_mma(const float* __restrict__ enc, const float* __restrict__ v,
         const float* __restrict__ bvd)
{
    extern __shared__ char smem[];
    const uint32_t sb = smem_u32(smem);
    const int tid  = threadIdx.x;
    const int wid  = tid >> 5;
    const int lane = tid & 31;
    const int warp_m = wid >> 2;      // 0..1 (32-token half)
    const int warp_n = wid & 3;       // 0..3 (32-n slice)

    const int t0g = blockIdx.x * 64;
    const int b   = t0g / T_;
    const int t0l = t0g % T_;

    // ---- stage enc tile (64 x 512 fp32 -> bf16 hi/lo, XOR-swizzled) ----
    #pragma unroll
    for (int i = tid; i < 64 * 128; i += 256) {
        int row = i >> 7, q = i & 127;   // q: float4 index within row
        float4 x = ((const float4*)(enc + (size_t)(t0g + row) * M_))[q];
        uint32_t h01 = pack2bf(x.x, x.y);
        uint32_t h23 = pack2bf(x.z, x.w);
        float h0 = __uint_as_float(h01 << 16);
        float h1 = __uint_as_float(h01 & 0xffff0000u);
        float h2 = __uint_as_float(h23 << 16);
        float h3 = __uint_as_float(h23 & 0xffff0000u);
        uint32_t l01 = pack2bf(x.x - h0, x.y - h1);
        uint32_t l23 = pack2bf(x.z - h2, x.w - h3);
        uint32_t off = (uint32_t)row * 1024 + ((((q >> 1)) ^ (row & 7)) << 4) + ((q & 1) << 3);
        *(uint2*)(smem + OFF_EH + off) = make_uint2(h01, h23);
        *(uint2*)(smem + OFF_EL + off) = make_uint2(l01, l23);
    }
    // ---- stage base hi/lo (bf16) and v pairs (f16x2) ----
    for (int n = tid; n < M_; n += 256) {
        float x = g_base[b * M_ + n];
        __nv_bfloat16 h = __float2bfloat16(x);
        float hf = __uint_as_float(((uint32_t)__bfloat16_as_ushort(h)) << 16);
        __nv_bfloat16 l = __float2bfloat16(x - hf);
        ((unsigned short*)(smem + OFF_BH))[n] = __bfloat16_as_ushort(h);
        ((unsigned short*)(smem + OFF_BL))[n] = __bfloat16_as_ushort(l);
    }
    if (tid < 256)
        ((uint32_t*)(smem + OFF_V2))[tid] = pack2h(v[2 * tid], v[2 * tid + 1]);
    if (tid < 64) ((float*)(smem + OFF_LG))[tid] = 0.f;

    // ---- per-thread ldmatrix base addresses ----
    const int la7  = lane & 7;
    const int la8  = (lane >> 3) & 1;
    const int la16 = (lane >> 4) & 1;
    const int arow = warp_m * 32 + la7 + la8 * 8;
    const uint32_t aH0 = sb + OFF_EH + (uint32_t)arow * 1024;
    const uint32_t aH1 = aH0 + 16 * 1024;
    const uint32_t aL0 = sb + OFF_EL + (uint32_t)arow * 1024;
    const uint32_t aL1 = aL0 + 16 * 1024;
    const int brow = warp_n * 32 + la7 + la16 * 8;
    const uint32_t bHa = sb + OFF_UH + (uint32_t)brow * 256;
    const uint32_t bHb = bHa + 16 * 256;
    const uint32_t bLa = sb + OFF_UL + (uint32_t)brow * 256;
    const uint32_t bLb = bLa + 16 * 256;

    // bias A fragment: 1.0 at k=0,1 for lane%4==0
    const uint32_t biasA = ((lane & 3) == 0) ? 0x3F803F80u : 0u;

    float rs[4] = {0.f, 0.f, 0.f, 0.f};   // [mt*2 + rowhalf] persistent token sums

    // ================= n-chunk loop =================
    for (int nc = 0; nc < 4; nc++) {
        float acc[2][4][4];
        #pragma unroll
        for (int a = 0; a < 2; a++)
            #pragma unroll
            for (int c = 0; c < 4; c++)
                #pragma unroll
                for (int d = 0; d < 4; d++) acc[a][c][d] = 0.f;

        for (int kt = 0; kt < 4; kt++) {
            __syncthreads();
            // load U tile [128n][128k] hi/lo (XOR-swizzled)
            #pragma unroll
            for (int i = tid; i < 2048; i += 256) {
                int r = i >> 4, c = i & 15;
                size_t src = (size_t)(nc * 128 + r) * M_ + kt * 128 + c * 8;
                uint32_t dst = (uint32_t)r * 256 + ((c ^ (r & 7)) << 4);
                *(uint4*)(smem + OFF_UH + dst) = *(const uint4*)(gU_hi + src);
                *(uint4*)(smem + OFF_UL + dst) = *(const uint4*)(gU_lo + src);
            }
            __syncthreads();

            #pragma unroll
            for (int ks = 0; ks < 8; ks++) {
                uint32_t aH[2][4], aL[2][4], bH[4][2], bL[4][2];
                uint32_t aoff = (uint32_t)(((kt * 16 + ks * 2 + la16) ^ la7) << 4);
                LDSM4(aH[0][0], aH[0][1], aH[0][2], aH[0][3], aH0 + aoff);
                LDSM4(aH[1][0], aH[1][1], aH[1][2], aH[1][3], aH1 + aoff);
                LDSM4(aL[0][0], aL[0][1], aL[0][2], aL[0][3], aL0 + aoff);
                LDSM4(aL[1][0], aL[1][1], aL[1][2], aL[1][3], aL1 + aoff);
                uint32_t boff = (uint32_t)(((ks * 2 + la8) ^ la7) << 4);
                LDSM4(bH[0][0], bH[0][1], bH[1][0], bH[1][1], bHa + boff);
                LDSM4(bH[2][0], bH[2][1], bH[3][0], bH[3][1], bHb + boff);
                LDSM4(bL[0][0], bL[0][1], bL[1][0], bL[1][1], bLa + boff);
                LDSM4(bL[2][0], bL[2][1], bL[3][0], bL[3][1], bLb + boff);
                #pragma unroll
                for (int mt = 0; mt < 2; mt++)
                    #pragma unroll
                    for (int nt = 0; nt < 4; nt++) {
                        mma16816(acc[mt][nt], aH[mt], bH[nt]);
                        mma16816(acc[mt][nt], aL[mt], bH[nt]);
                        mma16816(acc[mt][nt], aH[mt], bL[nt]);
                    }
            }
        }

        // ---- bias-in-GEMM: one extra k-step adds base_hi + base_lo ----
        {
            uint32_t aB[4] = {biasA, biasA, 0u, 0u};
            #pragma unroll
            for (int nt = 0; nt < 4; nt++) {
                int n = nc * 128 + warp_n * 32 + nt * 8 + (lane >> 2);
                uint32_t hi = ((const unsigned short*)(smem + OFF_BH))[n];
                uint32_t lo = ((const unsigned short*)(smem + OFF_BL))[n];
                uint32_t bB[2];
                bB[0] = ((lane & 3) == 0) ? (hi | (lo << 16)) : 0u;
                bB[1] = 0u;
                #pragma unroll
                for (int mt = 0; mt < 2; mt++)
                    mma16816(acc[mt][nt], aB, bB);
            }
        }

        // ---- epilogue: tanh(acc).v accumulated per token ----
        #pragma unroll
        for (int mt = 0; mt < 2; mt++) {
            uint32_t accA = 0u, accB = 0u;   // f16x2, <=4 adds before flush
            #pragma unroll
            for (int nt = 0; nt < 4; nt++) {
                int n0 = nc * 128 + warp_n * 32 + nt * 8 + 2 * (lane & 3);
                uint32_t v2 = ((const uint32_t*)(smem + OFF_V2))[n0 >> 1];
                uint32_t tA = tanh2(pack2h(acc[mt][nt][0], acc[mt][nt][1]));
                uint32_t tB = tanh2(pack2h(acc[mt][nt][2], acc[mt][nt][3]));
                accA = hfma2(tA, v2, accA);
                accB = hfma2(tB, v2, accB);
            }
            rs[mt * 2 + 0] += hsum2(accA);
            rs[mt * 2 + 1] += hsum2(accB);
        }
    }

    // ---- token reduction: 4 lanes (same token rows) then shared atomics ----
    #pragma unroll
    for (int j = 0; j < 4; j++) {
        rs[j] += __shfl_xor_sync(0xffffffffu, rs[j], 1);
        rs[j] += __shfl_xor_sync(0xffffffffu, rs[j], 2);
    }
    if ((lane & 3) == 0) {
        #pragma unroll
        for (int mt = 0; mt < 2; mt++) {
            int t = warp_m * 32 + mt * 16 + (lane >> 2);
            atomicAdd((float*)(smem + OFF_LG) + t,     rs[mt * 2 + 0]);
            atomicAdd((float*)(smem + OFF_LG) + t + 8, rs[mt * 2 + 1]);
        }
    }
    __syncthreads();
    if (tid < 64)
        g_logits[b * T_ + t0l + tid] = ((const float*)(smem + OFF_LG))[tid] + bvd[0];
}

// ============================================================
// Kernel 2: softmax over T per batch
// ============================================================
__global__ void softmax_kernel(float* __restrict__ out) {
    const int b = blockIdx.x;
    const int tid = threadIdx.x;
    const float* l = g_logits + b * T_;
    __shared__ float red[256];

    float vals[T_ / 256];
    float mx = -1e30f;
    #pragma unroll
    for (int j = 0; j < T_ / 256; j++) {
        vals[j] = l[tid + j * 256];
        mx = fmaxf(mx, vals[j]);
    }
    red[tid] = mx; __syncthreads();
    for (int s = 128; s; s >>= 1) {
        if (tid < s) red[tid] = fmaxf(red[tid], red[tid + s]);
        __syncthreads();
    }
    mx = red[0];
    __syncthreads();

    float sum = 0.f;
    #pragma unroll
    for (int j = 0; j < T_ / 256; j++) {
        vals[j] = expf(vals[j] - mx);
        sum += vals[j];
    }
    red[tid] = sum; __syncthreads();
    for (int s = 128; s; s >>= 1) {
        if (tid < s) red[tid] += red[tid + s];
        __syncthreads();
    }
    float inv = 1.0f / red[0];
    #pragma unroll
    for (int j = 0; j < T_ / 256; j++)
        out[b * T_ + tid + j * 256] = vals[j] * inv;
}

// ============================================================
extern "C" void kernel_launch(void* const* d_in, const int* in_sizes, int n_in,
                              void* d_out, int out_size)
{
    const float* h   = (const float*)d_in[0];
    const float* c   = (const float*)d_in[1];
    const float* enc = (const float*)d_in[2];
    const float* Wd  = (const float*)d_in[3];
    const float* bwd = (const float*)d_in[4];
    const float* U   = (const float*)d_in[5];
    const float* bud = (const float*)d_in[6];
    const float* v   = (const float*)d_in[7];
    const float* bvd = (const float*)d_in[8];
    float* out = (float*)d_out;

    cudaFuncSetAttribute(attn_mma, cudaFuncAttributeMaxDynamicSharedMemorySize, SMEM_TOTAL);

    prep_U<<<dim3(16, 16), 256>>>(U);
    base2<<<dim3(B_, 8), 256>>>(h, c, Wd, bwd, bud);
    attn_mma<<<R_ / 64, 256, SMEM_TOTAL>>>(enc, v, bvd);
    softmax_kernel<<<B_, 256>>>(out);
}